// round 10
// baseline (speedup 1.0000x reference)
#include <cuda_runtime.h>
#include <cstdint>

#define BB 64
#define TT 512
#define HH 768
#define KK 11
#define START_ID 9
#define END_ID 10
#define NEGV (-10000.0f)

#define NWARPS 12
#define NPROD 11
#define THREADS (NWARPS*32)

// ---- dynamic smem layout (bytes) ----
#define OFF_SWT     0                          // float[768*11] remapped weights
#define OFF_SFEAT   33792                      // float[(512+8)*12], stride 12
#define OFF_SDELTA  (33792+24960)              // float[512*12]
#define OFF_STRANS  (OFF_SDELTA+24576)         // float[121]
#define OFF_PATHSEG (OFF_STRANS+496)           // uchar[16][11][32]
#define OFF_ESEL    (OFF_PATHSEG+5632)         // uchar[16]
#define OFF_PROG    (OFF_ESEL+16)              // int[11]
#define OFF_MISC    (OFF_PROG+48)              // int lasttag
#define SMEM_TOTAL  (OFF_MISC+16)

// ---------------------------------------------------------------------------
// psi recompute: argmax_j (trans[tag][j] + delta[t-1][j]), first-max wins.
// Only j=0..8 can win for t>=2 (START/END preds masked to -1e4); at t=1 the
// winner is START for every target. Bit-exact vs reference.
// ---------------------------------------------------------------------------
__device__ __forceinline__ int psi_step(const float* __restrict__ strans,
                                        const float* __restrict__ sdelta,
                                        int t, int tag)
{
    if (t == 1) return START_ID;
    const float* tr = strans + tag * KK;
    const float* d = sdelta + (t - 1) * 12;
    float s[9];
#pragma unroll
    for (int j = 0; j < 9; j++) s[j] = tr[j] + d[j];
    float m = s[0];
#pragma unroll
    for (int j = 1; j < 9; j++) m = fmaxf(m, s[j]);
    unsigned msk = 0;
#pragma unroll
    for (int j = 0; j < 9; j++) msk |= (s[j] == m) ? (1u << j) : 0u;
    return __ffs(msk) - 1;
}

// ---------------------------------------------------------------------------
// Fused kernel: one block per batch. Warps 0..10 produce feats rows (GEMM),
// warp 11 runs the Viterbi scan chasing them. Then parallel backtrack.
// ---------------------------------------------------------------------------
extern __shared__ char dyn_smem[];

__global__ __launch_bounds__(THREADS, 1) void viterbi_fused(
    const float* __restrict__ embeds,   // [B,T,H]
    const float* __restrict__ W,        // [K,H]
    const float* __restrict__ bias,     // [K]
    const float* __restrict__ trans,    // [K,K]
    float* __restrict__ out)            // [B + B*T]
{
    const int b = blockIdx.x;
    const int tid = threadIdx.x;
    const int wid = tid >> 5;
    const int lane = tid & 31;

    float* sWt    = (float*)(dyn_smem + OFF_SWT);
    float* sfeat  = (float*)(dyn_smem + OFF_SFEAT);    // [t*12 + k]
    float* sdelta = (float*)(dyn_smem + OFF_SDELTA);   // [t*12 + slot]
    float* strans = (float*)(dyn_smem + OFF_STRANS);
    unsigned char (*s_pathseg)[KK][32] =
        (unsigned char (*)[KK][32])(dyn_smem + OFF_PATHSEG);
    unsigned char* s_esel = (unsigned char*)(dyn_smem + OFF_ESEL);
    volatile int* vprog   = (volatile int*)(dyn_smem + OFF_PROG);
    int* s_lasttag        = (int*)(dyn_smem + OFF_MISC);

    // ---- stage weights (remapped), transitions, init progress ----
    // h = 4*m + e  ->  sWt[(e*192 + m)*11 + k]  (producer LDS conflict-free)
    for (int i = tid; i < KK * HH; i += THREADS) {
        int k = i / HH, h = i - k * HH;
        int e = h & 3, m = h >> 2;
        sWt[(e * 192 + m) * KK + k] = W[i];
    }
    for (int i = tid; i < KK * KK; i += THREADS) strans[i] = trans[i];
    if (tid < NPROD) ((int*)(dyn_smem + OFF_PROG))[tid] = 0;
    __syncthreads();

    if (wid < NPROD) {
        // =========================== PRODUCERS ===========================
        const int w = wid;
        const float breg = (lane < KK) ? bias[lane] : 0.0f;
        const float* Abase = embeds + (size_t)b * TT * HH;

        for (int g = 0; g < 12; ++g) {
            const int tb = 1 + w + 44 * g;          // <= 495, always valid
            const float4* rp[4];
            bool val[4];
#pragma unroll
            for (int r = 0; r < 4; r++) {
                int t = tb + 11 * r;
                val[r] = (t <= TT - 1);
                rp[r] = (const float4*)(Abase + (size_t)(val[r] ? t : tb) * HH);
            }

            float acc[4][KK];
#pragma unroll
            for (int r = 0; r < 4; r++)
#pragma unroll
                for (int k = 0; k < KK; k++) acc[r][k] = 0.0f;

            float4 cur[4], nxt[4];
#pragma unroll
            for (int r = 0; r < 4; r++) cur[r] = rp[r][lane];

#pragma unroll
            for (int p = 0; p < 6; p++) {
                if (p < 5) {
#pragma unroll
                    for (int r = 0; r < 4; r++) nxt[r] = rp[r][(p + 1) * 32 + lane];
                }
#pragma unroll
                for (int e = 0; e < 4; e++) {
                    float wr[KK];
                    const float* wp = &sWt[(e * 192 + p * 32 + lane) * KK];
#pragma unroll
                    for (int k = 0; k < KK; k++) wr[k] = wp[k];
                    float a0 = (e == 0) ? cur[0].x : (e == 1) ? cur[0].y : (e == 2) ? cur[0].z : cur[0].w;
                    float a1 = (e == 0) ? cur[1].x : (e == 1) ? cur[1].y : (e == 2) ? cur[1].z : cur[1].w;
                    float a2 = (e == 0) ? cur[2].x : (e == 1) ? cur[2].y : (e == 2) ? cur[2].z : cur[2].w;
                    float a3 = (e == 0) ? cur[3].x : (e == 1) ? cur[3].y : (e == 2) ? cur[3].z : cur[3].w;
#pragma unroll
                    for (int k = 0; k < KK; k++) {
                        acc[0][k] = fmaf(a0, wr[k], acc[0][k]);
                        acc[1][k] = fmaf(a1, wr[k], acc[1][k]);
                        acc[2][k] = fmaf(a2, wr[k], acc[2][k]);
                        acc[3][k] = fmaf(a3, wr[k], acc[3][k]);
                    }
                }
#pragma unroll
                for (int r = 0; r < 4; r++) cur[r] = nxt[r];
            }

            // butterfly-reduce all 44 partials (result in every lane)
#pragma unroll
            for (int r = 0; r < 4; r++)
#pragma unroll
                for (int k = 0; k < KK; k++) {
                    float v = acc[r][k];
                    v += __shfl_xor_sync(0xffffffffu, v, 16);
                    v += __shfl_xor_sync(0xffffffffu, v, 8);
                    v += __shfl_xor_sync(0xffffffffu, v, 4);
                    v += __shfl_xor_sync(0xffffffffu, v, 2);
                    v += __shfl_xor_sync(0xffffffffu, v, 1);
                    acc[r][k] = v;
                }

            if (lane < KK) {
#pragma unroll
                for (int r = 0; r < 4; r++)
                    if (val[r]) sfeat[(tb + 11 * r) * 12 + lane] = acc[r][lane] + breg;
            }
            __threadfence_block();
            if (lane == 0) vprog[w] = tb + 33;
        }
    } else {
        // ============================= SCAN =============================
        const int target = (lane <= 8) ? lane : END_ID;     // lanes 9..31 -> END
        const int slot4 = ((lane <= 8) ? lane : 9) * 4;     // END in slot 9

        float tr0 = strans[target * KK + 0], tr1 = strans[target * KK + 1];
        float tr2 = strans[target * KK + 2], tr3 = strans[target * KK + 3];
        float tr4 = strans[target * KK + 4], tr5 = strans[target * KK + 5];
        float tr6 = strans[target * KK + 6], tr7 = strans[target * KK + 7];
        float tr8 = strans[target * KK + 8], tr9 = strans[target * KK + 9];

        const unsigned sd_base = (unsigned)__cvta_generic_to_shared(sdelta);

        int safe = 0;
#define WAIT_SAFE(X)                                                           \
        while (safe < (X)) {                                                   \
            int m0 = vprog[0];                                                 \
            m0 = min(m0, vprog[1]);  m0 = min(m0, vprog[2]);                   \
            m0 = min(m0, vprog[3]);  m0 = min(m0, vprog[4]);                   \
            m0 = min(m0, vprog[5]);  m0 = min(m0, vprog[6]);                   \
            m0 = min(m0, vprog[7]);  m0 = min(m0, vprog[8]);                   \
            m0 = min(m0, vprog[9]);  m0 = min(m0, vprog[10]);                  \
            safe = m0;                                                         \
            asm volatile("" ::: "memory");                                     \
        }

        WAIT_SAFE(13);

        float d0, d1, d2, d3, d4, d5, d6, d7, d8;

        // ---- t = 1 closed form: predecessor is START (certain) ----
        {
            float nd1 = (tr9 + 0.0f) + sfeat[12 + target];
            unsigned row1 = sd_base + 48;
            asm volatile("st.shared.f32 [%0], %1;"
                         :: "r"(row1 + slot4), "f"(nd1) : "memory");
            asm volatile("ld.shared.v4.f32 {%0,%1,%2,%3}, [%4];"
                         : "=f"(d0), "=f"(d1), "=f"(d2), "=f"(d3)
                         : "r"(row1) : "memory");
            asm volatile("ld.shared.v4.f32 {%0,%1,%2,%3}, [%4+16];"
                         : "=f"(d4), "=f"(d5), "=f"(d6), "=f"(d7)
                         : "r"(row1) : "memory");
            asm volatile("ld.shared.f32 %0, [%1+32];"
                         : "=f"(d8) : "r"(row1) : "memory");
        }

        float fbuf[6];
#pragma unroll
        for (int s = 0; s < 6; s++) fbuf[s] = sfeat[(2 + s) * 12 + target];
        const float* fpre = sfeat + 8 * 12 + target;

        unsigned addr = sd_base + 96;              // row 2 (written by U_=0)
        unsigned sd_store = addr + slot4;

#define VSTEP(U_, O0, O1)                                                      \
        {                                                                      \
            float f = fbuf[U_];                                                \
            fbuf[U_] = *fpre; fpre += 12;                                      \
            float s0 = tr0 + d0, s1 = tr1 + d1, s2 = tr2 + d2, s3 = tr3 + d3;  \
            float s4 = tr4 + d4, s5 = tr5 + d5, s6 = tr6 + d6, s7 = tr7 + d7;  \
            float s8v = tr8 + d8;                                              \
            float m01 = fmaxf(s0, s1), m23 = fmaxf(s2, s3);                    \
            float m45 = fmaxf(s4, s5), m67 = fmaxf(s6, s7);                    \
            float m = fmaxf(fmaxf(fmaxf(m01, m23), fmaxf(m45, m67)), s8v);     \
            float nd = m + f;                                                  \
            asm volatile("st.shared.f32 [%0+" #O0 "], %1;"                     \
                         :: "r"(sd_store), "f"(nd) : "memory");                \
            asm volatile("ld.shared.v4.f32 {%0,%1,%2,%3}, [%4+" #O0 "];"       \
                         : "=f"(d0), "=f"(d1), "=f"(d2), "=f"(d3)              \
                         : "r"(addr) : "memory");                              \
            asm volatile("ld.shared.v4.f32 {%0,%1,%2,%3}, [%4+" #O1 "];"       \
                         : "=f"(d4), "=f"(d5), "=f"(d6), "=f"(d7)              \
                         : "r"(addr) : "memory");                              \
            asm volatile("ld.shared.f32 %0, [%1+" #O1 "+16];"                  \
                         : "=f"(d8) : "r"(addr) : "memory");                   \
        }

        int t = 2;
        for (int it = 0; it < 85; ++it) {       // 85 * 6 = 510 steps, t = 2..511
            WAIT_SAFE(t + 11);
            VSTEP(0, 0, 16)
            VSTEP(1, 48, 64)
            VSTEP(2, 96, 112)
            VSTEP(3, 144, 160)
            VSTEP(4, 192, 208)
            VSTEP(5, 240, 256)
            addr += 288;
            sd_store += 288;
            t += 6;
        }
#undef VSTEP
#undef WAIT_SAFE

        __syncwarp();
        float dEND = sdelta[511 * 12 + 9];

        {
            float m01 = fmaxf(d0, d1), m23 = fmaxf(d2, d3);
            float m45 = fmaxf(d4, d5), m67 = fmaxf(d6, d7);
            float m = fmaxf(fmaxf(fmaxf(m01, m23), fmaxf(m45, m67)),
                            fmaxf(d8, dEND));
            unsigned msk = (d0 == m ? 1u : 0u) | (d1 == m ? 2u : 0u) |
                           (d2 == m ? 4u : 0u) | (d3 == m ? 8u : 0u) |
                           (d4 == m ? 16u : 0u) | (d5 == m ? 32u : 0u) |
                           (d6 == m ? 64u : 0u) | (d7 == m ? 128u : 0u) |
                           (d8 == m ? 256u : 0u) |
                           (dEND == m ? (1u << END_ID) : 0u);
            if (lane == 0) {
                out[b] = m;                       // score
                *s_lasttag = __ffs(msk) - 1;
            }
        }
    }
    __syncthreads();

    // ---- chunked backtrack, psi recomputed from stored deltas ----
    if (tid < 165) {                       // chunks 0..14 x 11 entry tags
        const int c = tid / KK;
        const int e = tid - c * KK;
        const int tb = 32 * c;
        int tag = e;                       // candidate tag at position tb+32
        for (int t = tb + 32; t > tb; --t) {
            tag = psi_step(strans, sdelta, t, tag);
            s_pathseg[c][e][t - 1 - tb] = (unsigned char)tag;
        }
    } else if (tid == 165) {               // chunk 15 from known last tag
        int tag = *s_lasttag;
        s_pathseg[15][0][31] = (unsigned char)tag;
        for (int t = TT - 1; t > 480; --t) {
            tag = psi_step(strans, sdelta, t, tag);
            s_pathseg[15][0][t - 1 - 480] = (unsigned char)tag;
        }
    }
    __syncthreads();

    if (tid == 0) {
        s_esel[15] = 0;
        int btag = s_pathseg[15][0][0];    // tag at position 480
        for (int c = 14; c >= 0; --c) {
            s_esel[c] = (unsigned char)btag;
            btag = s_pathseg[c][btag][0];  // tag at position 32c
        }
    }
    __syncthreads();

    for (int p = tid; p < TT; p += THREADS) {
        int c = p >> 5;
        out[BB + (size_t)b * TT + p] = (float)s_pathseg[c][s_esel[c]][p & 31];
    }
}

// ---------------------------------------------------------------------------
extern "C" void kernel_launch(void* const* d_in, const int* in_sizes, int n_in,
                              void* d_out, int out_size)
{
    const float* embeds = (const float*)d_in[0];   // [B,T,H]
    const float* W_fc   = (const float*)d_in[1];   // [K,H]
    const float* b_fc   = (const float*)d_in[2];   // [K]
    const float* trans  = (const float*)d_in[3];   // [K,K]
    float* out = (float*)d_out;

    cudaFuncSetAttribute(viterbi_fused,
                         cudaFuncAttributeMaxDynamicSharedMemorySize, SMEM_TOTAL);
    viterbi_fused<<<BB, THREADS, SMEM_TOTAL>>>(embeds, W_fc, b_fc, trans, out);
}